// round 1
// baseline (speedup 1.0000x reference)
#include <cuda_runtime.h>
#include <cstdint>

// ---------------------------------------------------------------------------
// PriorNetwork: nearest-neighbor (argmin of squared L2 over 100k train codes)
// + gather + 2-layer MLP (64 -> 512 relu -> {mu, logstd} 64 each).
//
// Pipeline (all on default stream, graph-capturable, no allocs):
//   k_init    : reset per-query packed (score,idx) keys
//   k_t2      : t2[n] = ||train[n]||^2
//   k_argmin  : tiled fp32 score GEMM + running min + atomicMin reduction
//   k_mlp     : gather chosen code, MLP, write [mu ; logstd]
// ---------------------------------------------------------------------------

#define D    64
#define H    512
#define QT   128     // queries per CTA tile
#define NT   128     // train rows per tile
#define TPAD 65      // padded row length for train smem tile (bank-conflict fix)

__device__ unsigned long long g_best[4096];
__device__ float g_t2[100480];

// Monotone encode of float for unsigned ordering (min float == min key)
__device__ __forceinline__ unsigned enc_f32(float f) {
    unsigned u = __float_as_uint(f);
    return (u & 0x80000000u) ? ~u : (u | 0x80000000u);
}

__global__ void k_init(int B) {
    int i = blockIdx.x * blockDim.x + threadIdx.x;
    if (i < B) g_best[i] = 0xFFFFFFFFFFFFFFFFULL;
}

__global__ void k_t2(const float* __restrict__ train, int N) {
    int n = blockIdx.x * blockDim.x + threadIdx.x;
    if (n < N) {
        const float4* r = (const float4*)(train + (size_t)n * D);
        float s = 0.f;
#pragma unroll
        for (int k = 0; k < D / 4; k++) {
            float4 v = r[k];
            s += v.x * v.x + v.y * v.y + v.z * v.z + v.w * v.w;
        }
        g_t2[n] = s;
    }
}

// Score s(q,n) = t2[n] - 2 * dot(codes[q], train[n]); per-query argmin.
// CTA tile: 128 queries x 128 train rows, 256 threads, 8x8 register tile.
__global__ void __launch_bounds__(256, 2)
k_argmin(const float* __restrict__ codes, const float* __restrict__ train,
         int N, int tiles_total, int tiles_per_split) {
    extern __shared__ float sm[];
    float* q_s = sm;              // [D][QT]   (transposed: d-major)
    float* t_s = sm + D * QT;     // [NT][TPAD] (natural layout, padded)

    const int tid = threadIdx.x;
    const int tq  = tid & 15;     // 16 query groups  x 8 q each = 128
    const int tn  = tid >> 4;     // 16 train groups  x 8 n each = 128
    const int qbase = blockIdx.x * QT;

    // Load + transpose the query tile once per CTA.
#pragma unroll
    for (int k = 0; k < 8; k++) {
        int lin = tid + k * 256;          // float4 index 0..2047
        int r   = lin >> 4;               // query row 0..127
        int c4  = lin & 15;               // float4 col 0..15
        float4 v = ((const float4*)codes)[(size_t)(qbase + r) * (D / 4) + c4];
        q_s[(c4 * 4 + 0) * QT + r] = v.x;
        q_s[(c4 * 4 + 1) * QT + r] = v.y;
        q_s[(c4 * 4 + 2) * QT + r] = v.z;
        q_s[(c4 * 4 + 3) * QT + r] = v.w;
    }

    float bv[8];
    int   bi[8];
#pragma unroll
    for (int i = 0; i < 8; i++) { bv[i] = 3.4e38f; bi[i] = 0x7FFFFFFF; }

    const int t0 = blockIdx.y * tiles_per_split;
    const int t1 = min(t0 + tiles_per_split, tiles_total);

    for (int t = t0; t < t1; t++) {
        const int n0 = t * NT;
        __syncthreads();
        // Load train tile [NT][D] (rows padded to TPAD), zero-fill past N.
#pragma unroll
        for (int k = 0; k < 8; k++) {
            int lin = tid + k * 256;
            int r   = lin >> 4;
            int c4  = lin & 15;
            int n   = n0 + r;
            float4 v = (n < N) ? ((const float4*)train)[(size_t)n * (D / 4) + c4]
                               : make_float4(0.f, 0.f, 0.f, 0.f);
            float* dst = t_s + r * TPAD + c4 * 4;
            dst[0] = v.x; dst[1] = v.y; dst[2] = v.z; dst[3] = v.w;
        }
        __syncthreads();

        float acc[8][8];
#pragma unroll
        for (int i = 0; i < 8; i++)
#pragma unroll
            for (int j = 0; j < 8; j++) acc[i][j] = 0.f;

#pragma unroll 4
        for (int d = 0; d < D; d++) {
            float4 a0 = *(const float4*)&q_s[d * QT + tq * 8];
            float4 a1 = *(const float4*)&q_s[d * QT + tq * 8 + 4];
            float a[8] = {a0.x, a0.y, a0.z, a0.w, a1.x, a1.y, a1.z, a1.w};
            float b[8];
#pragma unroll
            for (int j = 0; j < 8; j++) b[j] = t_s[(tn * 8 + j) * TPAD + d];
#pragma unroll
            for (int i = 0; i < 8; i++)
#pragma unroll
                for (int j = 0; j < 8; j++)
                    acc[i][j] = fmaf(a[i], b[j], acc[i][j]);
        }

        // Epilogue: fold in t2, update running min (ascending n => strict <
        // preserves lowest-index tie-break within a thread).
#pragma unroll
        for (int j = 0; j < 8; j++) {
            int n = n0 + tn * 8 + j;
            if (n < N) {
                float t2v = g_t2[n];
#pragma unroll
                for (int i = 0; i < 8; i++) {
                    float s = fmaf(-2.f, acc[i][j], t2v);
                    if (s < bv[i]) { bv[i] = s; bi[i] = n; }
                }
            }
        }
    }

    // CTA-level reduction (packed key ties -> lowest index), then global.
    __syncthreads();
    unsigned long long* sb = (unsigned long long*)sm;  // reuse smem (128 keys)
    if (tid < QT) sb[tid] = 0xFFFFFFFFFFFFFFFFULL;
    __syncthreads();
#pragma unroll
    for (int i = 0; i < 8; i++) {
        unsigned long long key =
            ((unsigned long long)enc_f32(bv[i]) << 32) | (unsigned)bi[i];
        atomicMin(&sb[tq * 8 + i], key);
    }
    __syncthreads();
    if (tid < QT) atomicMin(&g_best[qbase + tid], sb[tid]);
}

// One CTA per query: gather chosen code, h1 = relu(x@W1+b1),
// mu = h1@Wu+bu, logstd = h1@Ws+bs. Weights are L2-resident (128 KB each).
__global__ void k_mlp(const float* __restrict__ train,
                      const float* __restrict__ W1, const float* __restrict__ b1,
                      const float* __restrict__ Wu, const float* __restrict__ bu,
                      const float* __restrict__ Ws, const float* __restrict__ bs,
                      float* __restrict__ out, int B) {
    __shared__ float x_s[D];
    __shared__ float h_s[H];
    const int q   = blockIdx.x;
    const int tid = threadIdx.x;  // 256

    unsigned chosen = (unsigned)(g_best[q] & 0xFFFFFFFFULL);
    if (tid < D) x_s[tid] = train[(size_t)chosen * D + tid];
    __syncthreads();

    // h1: each thread computes columns tid and tid+256.
    {
        float a0 = 0.f, a1 = 0.f;
#pragma unroll 8
        for (int d = 0; d < D; d++) {
            float x = x_s[d];
            a0 = fmaf(x, W1[d * H + tid],       a0);
            a1 = fmaf(x, W1[d * H + tid + 256], a1);
        }
        h_s[tid]       = fmaxf(a0 + b1[tid],       0.f);
        h_s[tid + 256] = fmaxf(a1 + b1[tid + 256], 0.f);
    }
    __syncthreads();

    // mu (which=0) and logstd (which=1): 128 active threads.
    if (tid < 2 * D) {
        const int d     = tid & (D - 1);
        const int which = tid >> 6;
        const float* W  = which ? Ws : Wu;
        const float* bb = which ? bs : bu;
        float a0 = 0.f, a1 = 0.f, a2 = 0.f, a3 = 0.f;
#pragma unroll 4
        for (int h = 0; h < H; h += 4) {
            a0 = fmaf(h_s[h + 0], W[(h + 0) * D + d], a0);
            a1 = fmaf(h_s[h + 1], W[(h + 1) * D + d], a1);
            a2 = fmaf(h_s[h + 2], W[(h + 2) * D + d], a2);
            a3 = fmaf(h_s[h + 3], W[(h + 3) * D + d], a3);
        }
        out[(size_t)which * B * D + (size_t)q * D + d] = (a0 + a1) + (a2 + a3) + bb[d];
    }
}

extern "C" void kernel_launch(void* const* d_in, const int* in_sizes, int n_in,
                              void* d_out, int out_size) {
    const float* codes = (const float*)d_in[0];
    const float* train = (const float*)d_in[1];
    const float* W1    = (const float*)d_in[2];
    const float* b1    = (const float*)d_in[3];
    const float* Wu    = (const float*)d_in[4];
    const float* bu    = (const float*)d_in[5];
    const float* Ws    = (const float*)d_in[6];
    const float* bs    = (const float*)d_in[7];
    float* out = (float*)d_out;

    const int B = in_sizes[0] / D;   // 2048
    const int N = in_sizes[1] / D;   // 100000

    k_init<<<(B + 255) / 256, 256>>>(B);
    k_t2<<<(N + 255) / 256, 256>>>(train, N);

    const int tiles_total = (N + NT - 1) / NT;          // 782
    const int qtiles      = (B + QT - 1) / QT;          // 16
    const int nsplits     = 18;                         // 16*18=288 CTAs, 1 wave @ 2/SM
    const int tps         = (tiles_total + nsplits - 1) / nsplits;

    const size_t smem = (size_t)(D * QT + NT * TPAD) * sizeof(float);  // ~66 KB
    cudaFuncSetAttribute(k_argmin, cudaFuncAttributeMaxDynamicSharedMemorySize,
                         (int)smem);
    dim3 grid(qtiles, nsplits);
    k_argmin<<<grid, 256, smem>>>(codes, train, N, tiles_total, tps);

    k_mlp<<<B, 256>>>(train, W1, b1, Wu, bu, Ws, bs, out, B);
}

// round 2
// speedup vs baseline: 1.0245x; 1.0245x over previous
#include <cuda_runtime.h>
#include <cstdint>

// ---------------------------------------------------------------------------
// PriorNetwork: argmin of squared L2 over 100k train codes + gather + MLP.
//
// Round 2: packed fp32 (fma.rn.f32x2) argmin mainloop (2 exact fp32 FMAs per
// issue), cp.async double-buffered train tiles, batched MLP (16 queries/CTA).
// ---------------------------------------------------------------------------

#define D    64
#define H    512
#define QT   128     // queries per CTA tile
#define NT   128     // train rows per tile
#define TPAD 68      // padded row stride (floats): 272B, 16B-aligned for cp.async
#define QB   16      // queries per MLP CTA

__device__ unsigned long long g_best[4096];
__device__ float g_t2[100480];

// ---- helpers --------------------------------------------------------------

__device__ __forceinline__ unsigned enc_f32(float f) {
    unsigned u = __float_as_uint(f);
    return (u & 0x80000000u) ? ~u : (u | 0x80000000u);
}

__device__ __forceinline__ unsigned long long pk2(float x, float y) {
    unsigned long long r;
    asm("mov.b64 %0, {%1, %2};" : "=l"(r) : "f"(x), "f"(y));
    return r;
}
__device__ __forceinline__ void upk2(unsigned long long v, float& x, float& y) {
    asm("mov.b64 {%0, %1}, %2;" : "=f"(x), "=f"(y) : "l"(v));
}
// d = a * b + d, packed 2 x fp32 (exact fp32 rounding per lane)
__device__ __forceinline__ void fma2(unsigned long long& d_, unsigned long long a,
                                     unsigned long long b) {
    asm("fma.rn.f32x2 %0, %1, %2, %0;" : "+l"(d_) : "l"(a), "l"(b));
}

__device__ __forceinline__ unsigned smem_u32(const void* p) {
    return (unsigned)__cvta_generic_to_shared(p);
}
__device__ __forceinline__ void cp16(unsigned dst, const void* src, int srcsz) {
    asm volatile("cp.async.cg.shared.global [%0], [%1], 16, %2;"
                 :: "r"(dst), "l"(src), "r"(srcsz));
}
#define CP_COMMIT() asm volatile("cp.async.commit_group;")
#define CP_WAIT0()  asm volatile("cp.async.wait_group 0;")

// ---- small kernels --------------------------------------------------------

__global__ void k_init(int B) {
    int i = blockIdx.x * blockDim.x + threadIdx.x;
    if (i < B) g_best[i] = 0xFFFFFFFFFFFFFFFFULL;
}

__global__ void k_t2(const float* __restrict__ train, int N) {
    int n = blockIdx.x * blockDim.x + threadIdx.x;
    if (n < N) {
        const float4* r = (const float4*)(train + (size_t)n * D);
        float s = 0.f;
#pragma unroll
        for (int k = 0; k < D / 4; k++) {
            float4 v = r[k];
            s += v.x * v.x + v.y * v.y + v.z * v.z + v.w * v.w;
        }
        g_t2[n] = s;
    }
}

// ---- argmin ---------------------------------------------------------------
// Score s(q,n) = t2[n] - 2*dot(q,t). CTA tile 128q x 128n, 256 threads,
// 8x8 register tile with accumulators packed in f32x2 pairs along q.

__device__ __forceinline__ void load_tile_async(float* buf, const float* train,
                                                int n0, int N, int tid) {
#pragma unroll
    for (int k = 0; k < 8; k++) {
        int lin = tid + k * 256;          // float4 slot 0..2047
        int r   = lin >> 4;               // tile row 0..127
        int c4  = lin & 15;               // float4 col 0..15
        int n   = n0 + r;
        const float* src = train + (size_t)min(n, N - 1) * D + c4 * 4;
        cp16(smem_u32(buf + r * TPAD + c4 * 4), src, (n < N) ? 16 : 0);
    }
}

__global__ void __launch_bounds__(256, 1)
k_argmin(const float* __restrict__ codes, const float* __restrict__ train,
         int N, int tiles_total, int tiles_per_split) {
    extern __shared__ float sm[];
    float* q_s   = sm;                        // [D][QT] transposed, 32 KB
    float* tbuf0 = sm + D * QT;               // [NT][TPAD]
    float* tbuf1 = tbuf0 + NT * TPAD;         // [NT][TPAD]

    const int tid = threadIdx.x;
    const int tq  = tid & 15;                 // query group (8 q, contiguous)
    const int tn  = tid >> 4;                 // train group (8 n, stride 16)
    const int qbase = blockIdx.x * QT;

    const int t0 = blockIdx.y * tiles_per_split;
    const int t1 = min(t0 + tiles_per_split, tiles_total);

    // Prefetch first train tile.
    load_tile_async(tbuf0, train, t0 * NT, N, tid);
    CP_COMMIT();

    // Load + transpose query tile (d-major).
#pragma unroll
    for (int k = 0; k < 8; k++) {
        int lin = tid + k * 256;
        int r   = lin >> 4;
        int c4  = lin & 15;
        float4 v = ((const float4*)codes)[(size_t)(qbase + r) * (D / 4) + c4];
        q_s[(c4 * 4 + 0) * QT + r] = v.x;
        q_s[(c4 * 4 + 1) * QT + r] = v.y;
        q_s[(c4 * 4 + 2) * QT + r] = v.z;
        q_s[(c4 * 4 + 3) * QT + r] = v.w;
    }

    float bv[8];
    int   bi[8];
#pragma unroll
    for (int i = 0; i < 8; i++) { bv[i] = 3.4e38f; bi[i] = 0x7FFFFFFF; }

    CP_WAIT0();
    __syncthreads();

    for (int t = t0; t < t1; t++) {
        float* cur = ((t - t0) & 1) ? tbuf1 : tbuf0;
        float* nxt = ((t - t0) & 1) ? tbuf0 : tbuf1;
        const int n0 = t * NT;

        if (t + 1 < t1) load_tile_async(nxt, train, (t + 1) * NT, N, tid);
        CP_COMMIT();

        // acc2[i2][j]: packed pair {q=2*i2, q=2*i2+1} x train j
        unsigned long long acc2[4][8];
#pragma unroll
        for (int i2 = 0; i2 < 4; i2++)
#pragma unroll
            for (int j = 0; j < 8; j++) acc2[i2][j] = 0ULL;

#pragma unroll 8
        for (int d = 0; d < D; d++) {
            float4 A0 = *(const float4*)&q_s[d * QT + tq * 8];
            float4 A1 = *(const float4*)&q_s[d * QT + tq * 8 + 4];
            unsigned long long pa[4];
            pa[0] = pk2(A0.x, A0.y);
            pa[1] = pk2(A0.z, A0.w);
            pa[2] = pk2(A1.x, A1.y);
            pa[3] = pk2(A1.z, A1.w);
            unsigned long long pb[8];
#pragma unroll
            for (int j = 0; j < 8; j++) {
                float b = cur[(tn + 16 * j) * TPAD + d];   // rows stride 16
                pb[j] = pk2(b, b);
            }
#pragma unroll
            for (int i2 = 0; i2 < 4; i2++)
#pragma unroll
                for (int j = 0; j < 8; j++)
                    fma2(acc2[i2][j], pa[i2], pb[j]);
        }

        // Epilogue: s = t2[n] - 2*dot; running min (j ascending => n ascending
        // within a thread, strict < keeps lowest index).
#pragma unroll
        for (int j = 0; j < 8; j++) {
            int n = n0 + tn + 16 * j;
            if (n < N) {
                float t2v = g_t2[n];
#pragma unroll
                for (int i2 = 0; i2 < 4; i2++) {
                    float d0, d1;
                    upk2(acc2[i2][j], d0, d1);
                    float s0 = fmaf(-2.f, d0, t2v);
                    float s1 = fmaf(-2.f, d1, t2v);
                    if (s0 < bv[2 * i2])     { bv[2 * i2]     = s0; bi[2 * i2]     = n; }
                    if (s1 < bv[2 * i2 + 1]) { bv[2 * i2 + 1] = s1; bi[2 * i2 + 1] = n; }
                }
            }
        }

        CP_WAIT0();
        __syncthreads();
    }

    // CTA reduction (packed key: ties -> lowest index), then global.
    unsigned long long* sb = (unsigned long long*)sm;  // reuse smem
    if (tid < QT) sb[tid] = 0xFFFFFFFFFFFFFFFFULL;
    __syncthreads();
#pragma unroll
    for (int i = 0; i < 8; i++) {
        unsigned long long key =
            ((unsigned long long)enc_f32(bv[i]) << 32) | (unsigned)bi[i];
        atomicMin(&sb[tq * 8 + i], key);
    }
    __syncthreads();
    if (tid < QT) atomicMin(&g_best[qbase + tid], sb[tid]);
}

// ---- MLP: 16 queries per CTA (weights read once per CTA) ------------------

__global__ void __launch_bounds__(256)
k_mlp(const float* __restrict__ train,
      const float* __restrict__ W1, const float* __restrict__ b1,
      const float* __restrict__ Wu, const float* __restrict__ bu,
      const float* __restrict__ Ws, const float* __restrict__ bs,
      float* __restrict__ out, int B) {
    __shared__ float x_s[QB][D];
    __shared__ float h_s[QB][H];
    const int qb  = blockIdx.x * QB;
    const int tid = threadIdx.x;

    // Gather chosen codes (16B granules).
    if (tid < QB * (D / 4)) {
        int q  = tid >> 4;
        int c4 = tid & 15;
        unsigned ch = (unsigned)(g_best[qb + q] & 0xFFFFFFFFULL);
        ((float4*)&x_s[q][0])[c4] = ((const float4*)train)[(size_t)ch * (D / 4) + c4];
    }
    __syncthreads();

    // Stage 1: h = relu(x @ W1 + b1); thread owns columns tid, tid+256.
    {
        float a0[QB], a1[QB];
#pragma unroll
        for (int q = 0; q < QB; q++) { a0[q] = 0.f; a1[q] = 0.f; }
        const int c0 = tid, c1 = tid + 256;
#pragma unroll 4
        for (int d = 0; d < D; d++) {
            float w0 = W1[d * H + c0];
            float w1 = W1[d * H + c1];
#pragma unroll
            for (int q = 0; q < QB; q++) {
                float x = x_s[q][d];
                a0[q] = fmaf(x, w0, a0[q]);
                a1[q] = fmaf(x, w1, a1[q]);
            }
        }
        float bb0 = b1[c0], bb1 = b1[c1];
#pragma unroll
        for (int q = 0; q < QB; q++) {
            h_s[q][c0] = fmaxf(a0[q] + bb0, 0.f);
            h_s[q][c1] = fmaxf(a1[q] + bb1, 0.f);
        }
    }
    __syncthreads();

    // Stage 2: mu/logstd. Thread -> (d, which, 8-query half).
    {
        const int d     = tid & 63;
        const int which = (tid >> 6) & 1;
        const int half  = tid >> 7;            // 0 or 1
        const float* W  = which ? Ws : Wu;
        const float* bb = which ? bs : bu;
        float acc[8];
#pragma unroll
        for (int q = 0; q < 8; q++) acc[q] = 0.f;
#pragma unroll 4
        for (int h = 0; h < H; h++) {
            float w = W[h * D + d];
#pragma unroll
            for (int q = 0; q < 8; q++)
                acc[q] = fmaf(h_s[half * 8 + q][h], w, acc[q]);
        }
        float bbv = bb[d];
#pragma unroll
        for (int q = 0; q < 8; q++)
            out[(size_t)which * B * D + (size_t)(qb + half * 8 + q) * D + d] =
                acc[q] + bbv;
    }
}

// ---- launch ---------------------------------------------------------------

extern "C" void kernel_launch(void* const* d_in, const int* in_sizes, int n_in,
                              void* d_out, int out_size) {
    const float* codes = (const float*)d_in[0];
    const float* train = (const float*)d_in[1];
    const float* W1    = (const float*)d_in[2];
    const float* b1    = (const float*)d_in[3];
    const float* Wu    = (const float*)d_in[4];
    const float* bu    = (const float*)d_in[5];
    const float* Ws    = (const float*)d_in[6];
    const float* bs    = (const float*)d_in[7];
    float* out = (float*)d_out;

    const int B = in_sizes[0] / D;   // 2048
    const int N = in_sizes[1] / D;   // 100000

    k_init<<<(B + 255) / 256, 256>>>(B);
    k_t2<<<(N + 255) / 256, 256>>>(train, N);

    const int tiles_total = (N + NT - 1) / NT;            // 782
    const int qtiles      = (B + QT - 1) / QT;            // 16
    const int nsplits     = 9;                            // 144 CTAs = 1/SM wave
    const int tps         = (tiles_total + nsplits - 1) / nsplits;

    const size_t smem = (size_t)(D * QT + 2 * NT * TPAD) * sizeof(float); // 100 KB
    cudaFuncSetAttribute(k_argmin, cudaFuncAttributeMaxDynamicSharedMemorySize,
                         (int)smem);
    dim3 grid(qtiles, nsplits);
    k_argmin<<<grid, 256, smem>>>(codes, train, N, tiles_total, tps);

    k_mlp<<<B / QB, 256>>>(train, W1, b1, Wu, bu, Ws, bs, out, B);
}

// round 3
// speedup vs baseline: 1.7285x; 1.6873x over previous
#include <cuda_runtime.h>
#include <cstdint>

// ---------------------------------------------------------------------------
// PriorNetwork round 3: TF32 tensor-core approximate distances + epsilon
// candidate rescue + exact fp32 rescore + batched MLP.
// ---------------------------------------------------------------------------

#define D     64
#define H     512
#define QT    128      // queries per score CTA
#define NT    128      // train rows per tile
#define CAP   1024     // candidate cap per query
#define EPS   0.5f
#define NPAD  100480
#define BQ    2048

__device__ unsigned long long g_best[BQ];
__device__ float g_t2[NPAD];
__device__ int   g_ccnt[BQ];
__device__ int   g_cand[BQ * CAP];

// ---- helpers --------------------------------------------------------------

__device__ __forceinline__ unsigned enc_f32(float f) {
    unsigned u = __float_as_uint(f);
    return (u & 0x80000000u) ? ~u : (u | 0x80000000u);
}
__device__ __forceinline__ float dec_f32(unsigned e) {
    unsigned u = (e & 0x80000000u) ? (e ^ 0x80000000u) : ~e;
    return __uint_as_float(u);
}
__device__ __forceinline__ uint32_t to_tf32(float f) {
    uint32_t r;
    asm("cvt.rna.tf32.f32 %0, %1;" : "=r"(r) : "f"(f));
    return r;
}
__device__ __forceinline__ void mma_tf32(float* c, const uint32_t* a,
                                         uint32_t b0, uint32_t b1) {
    asm("mma.sync.aligned.m16n8k8.row.col.f32.tf32.tf32.f32 "
        "{%0,%1,%2,%3}, {%4,%5,%6,%7}, {%8,%9}, {%0,%1,%2,%3};"
        : "+f"(c[0]), "+f"(c[1]), "+f"(c[2]), "+f"(c[3])
        : "r"(a[0]), "r"(a[1]), "r"(a[2]), "r"(a[3]), "r"(b0), "r"(b1));
}

// ---- small kernels --------------------------------------------------------

__global__ void k_initcnt(int B) {
    int i = blockIdx.x * blockDim.x + threadIdx.x;
    if (i < B) g_ccnt[i] = 0;
}

__global__ void k_t2(const float* __restrict__ train, int N) {
    int n = blockIdx.x * blockDim.x + threadIdx.x;
    if (n < NPAD) {
        if (n < N) {
            const float4* r = (const float4*)(train + (size_t)n * D);
            float s = 0.f;
#pragma unroll
            for (int k = 0; k < D / 4; k++) {
                float4 v = r[k];
                s += v.x * v.x + v.y * v.y + v.z * v.z + v.w * v.w;
            }
            g_t2[n] = s;
        } else {
            g_t2[n] = 3.0e38f;   // pad rows never win / never append
        }
    }
}

// ---- k_score: tf32 mma distances + candidate rescue -----------------------
// Smem word layout (uint32 words):
//   tb[2][128n * 80]  train tiles, slot(n, r=k%4, u=k/4) = n*80 + r*20 + u
//   t2b[2][128]       tile t2 values (float)
//   cmin[128]         per-query running min (enc'd), persistent per CTA
#define TBW   10240
#define OFF_T2   (2 * TBW)
#define OFF_CMIN (OFF_T2 + 2 * 128)
#define SMW   (OFF_CMIN + 128)

__device__ __forceinline__ void ldg_tile(float4 v[8], float4& t2r,
                                         const float* __restrict__ train,
                                         int n0, int N, int tid) {
#pragma unroll
    for (int k = 0; k < 8; k++) {
        int lin = tid + (k << 8);
        int nl  = lin >> 4;
        int c4  = lin & 15;
        int n   = n0 + nl;
        v[k] = make_float4(0.f, 0.f, 0.f, 0.f);
        if (n < N)
            v[k] = __ldg(&((const float4*)train)[(size_t)n * (D / 4) + c4]);
    }
    if (tid < 32) t2r = *(const float4*)&g_t2[n0 + tid * 4];
}

__device__ __forceinline__ void sts_tile(uint32_t* __restrict__ buf,
                                         float* __restrict__ t2buf,
                                         const float4 v[8], float4 t2r, int tid) {
#pragma unroll
    for (int k = 0; k < 8; k++) {
        int lin = tid + (k << 8);
        int nl  = lin >> 4;
        int c4  = lin & 15;
        uint32_t* p = buf + nl * 80 + c4;
        p[0]  = to_tf32(v[k].x);
        p[20] = to_tf32(v[k].y);
        p[40] = to_tf32(v[k].z);
        p[60] = to_tf32(v[k].w);
    }
    if (tid < 32) *(float4*)&t2buf[tid * 4] = t2r;
}

__global__ void __launch_bounds__(256, 1)
k_score(const float* __restrict__ codes, const float* __restrict__ train,
        int N, int tiles_total, int tps) {
    extern __shared__ uint32_t sw[];
    float*    t2b  = (float*)(sw + OFF_T2);
    unsigned* cmin = (unsigned*)(sw + OFF_CMIN);

    const int tid  = threadIdx.x;
    const int lane = tid & 31;
    const int wid  = tid >> 5;
    const int wm   = wid >> 1;       // 0..3 : m32 strip
    const int wn   = wid & 1;        // 0..1 : n64 strip
    const int g    = lane >> 2;      // quad row 0..7
    const int r4   = lane & 3;       // quad col 0..3
    const int qbase = blockIdx.x * QT;

    const int t0 = blockIdx.y * tps;
    const int t1 = min(t0 + tps, tiles_total);
    if (t0 >= t1) return;

    if (tid < QT) cmin[tid] = 0xFFFFFFFFu;

    // Prefetch first tile.
    float4 v[8]; float4 t2r;
    ldg_tile(v, t2r, train, t0 * NT, N, tid);

    // Hoist A fragments (queries) into registers: afr[mi][s][0..3]
    uint32_t afr[2][8][4];
#pragma unroll
    for (int mi = 0; mi < 2; mi++) {
        int row0 = qbase + wm * 32 + mi * 16 + g;
#pragma unroll
        for (int s = 0; s < 8; s++) {
            afr[mi][s][0] = to_tf32(__ldg(&codes[(size_t)row0 * D + s * 8 + r4]));
            afr[mi][s][1] = to_tf32(__ldg(&codes[(size_t)(row0 + 8) * D + s * 8 + r4]));
            afr[mi][s][2] = to_tf32(__ldg(&codes[(size_t)row0 * D + s * 8 + r4 + 4]));
            afr[mi][s][3] = to_tf32(__ldg(&codes[(size_t)(row0 + 8) * D + s * 8 + r4 + 4]));
        }
    }

    sts_tile(sw, t2b, v, t2r, tid);
    __syncthreads();

    // Row (query) each accum slot belongs to: slot = mi*2 + (c>>1)
    int rowl[4];
#pragma unroll
    for (int slot = 0; slot < 4; slot++)
        rowl[slot] = wm * 32 + (slot >> 1) * 16 + g + (slot & 1) * 8;

    for (int t = t0; t < t1; t++) {
        const int p = (t - t0) & 1;
        uint32_t* cur  = sw + p * TBW;
        uint32_t* nxt  = sw + (p ^ 1) * TBW;
        float*    t2c  = t2b + p * 128;
        float*    t2n  = t2b + (p ^ 1) * 128;
        const int n0 = t * NT;

        if (t + 1 < t1) ldg_tile(v, t2r, train, (t + 1) * NT, N, tid);

        float acc[2][8][4];
#pragma unroll
        for (int mi = 0; mi < 2; mi++)
#pragma unroll
            for (int j = 0; j < 8; j++)
#pragma unroll
                for (int c = 0; c < 4; c++) acc[mi][j][c] = 0.f;

#pragma unroll
        for (int j = 0; j < 8; j++) {
            const uint32_t* bp = cur + (wn * 64 + j * 8 + g) * 80 + r4 * 20;
            uint4 w0 = *(const uint4*)(bp + 0);
            uint4 w1 = *(const uint4*)(bp + 4);
            uint4 w2 = *(const uint4*)(bp + 8);
            uint4 w3 = *(const uint4*)(bp + 12);
            uint32_t bb[16] = {w0.x, w0.y, w0.z, w0.w, w1.x, w1.y, w1.z, w1.w,
                               w2.x, w2.y, w2.z, w2.w, w3.x, w3.y, w3.z, w3.w};
#pragma unroll
            for (int s = 0; s < 8; s++) {
                mma_tf32(acc[0][j], afr[0][s], bb[2 * s], bb[2 * s + 1]);
                mma_tf32(acc[1][j], afr[1][s], bb[2 * s], bb[2 * s + 1]);
            }
        }

        // Row minima -> shared running min.
        float rmin[4] = {3.4e38f, 3.4e38f, 3.4e38f, 3.4e38f};
#pragma unroll
        for (int mi = 0; mi < 2; mi++)
#pragma unroll
            for (int j = 0; j < 8; j++)
#pragma unroll
                for (int c = 0; c < 4; c++) {
                    int nl = wn * 64 + j * 8 + r4 * 2 + (c & 1);
                    float s = fmaf(-2.f, acc[mi][j][c], t2c[nl]);
                    int slot = mi * 2 + (c >> 1);
                    rmin[slot] = fminf(rmin[slot], s);
                }
#pragma unroll
        for (int slot = 0; slot < 4; slot++) {
            rmin[slot] = fminf(rmin[slot], __shfl_xor_sync(0xffffffffu, rmin[slot], 1));
            rmin[slot] = fminf(rmin[slot], __shfl_xor_sync(0xffffffffu, rmin[slot], 2));
        }
        if (r4 == 0) {
#pragma unroll
            for (int slot = 0; slot < 4; slot++)
                atomicMin(&cmin[rowl[slot]], enc_f32(rmin[slot]));
        }
        __syncthreads();

        // Candidate rescue vs. running min (covers true argmin: ŝ(n*) <= m + EPS).
        float thr[4];
#pragma unroll
        for (int slot = 0; slot < 4; slot++)
            thr[slot] = dec_f32(cmin[rowl[slot]]) + EPS;
#pragma unroll
        for (int mi = 0; mi < 2; mi++)
#pragma unroll
            for (int j = 0; j < 8; j++)
#pragma unroll
                for (int c = 0; c < 4; c++) {
                    int nl = wn * 64 + j * 8 + r4 * 2 + (c & 1);
                    float s = fmaf(-2.f, acc[mi][j][c], t2c[nl]);
                    int slot = mi * 2 + (c >> 1);
                    if (s <= thr[slot]) {
                        int q = qbase + rowl[slot];
                        int pos = atomicAdd(&g_ccnt[q], 1);
                        if (pos < CAP) g_cand[q * CAP + pos] = n0 + nl;
                    }
                }

        if (t + 1 < t1) sts_tile(nxt, t2n, v, t2r, tid);
        __syncthreads();
    }
}

// ---- exact fp32 rescore over candidates (one warp per query) --------------

__global__ void __launch_bounds__(256)
k_rescore(const float* __restrict__ codes, const float* __restrict__ train,
          int B) {
    const int lane = threadIdx.x & 31;
    const int q = blockIdx.x * 8 + (threadIdx.x >> 5);
    if (q >= B) return;

    float4 qv[16];
#pragma unroll
    for (int i = 0; i < 16; i++)
        qv[i] = __ldg(&((const float4*)codes)[(size_t)q * 16 + i]);

    unsigned long long best = 0xFFFFFFFFFFFFFFFFULL;
    int cnt = min(g_ccnt[q], CAP);
    for (int i = lane; i < cnt; i += 32) {
        int n = g_cand[q * CAP + i];
        const float4* tr = (const float4*)(train + (size_t)n * D);
        float dot = 0.f;
#pragma unroll
        for (int k = 0; k < 16; k++) {
            float4 tv = __ldg(&tr[k]);
            dot = fmaf(qv[k].x, tv.x, dot);
            dot = fmaf(qv[k].y, tv.y, dot);
            dot = fmaf(qv[k].z, tv.z, dot);
            dot = fmaf(qv[k].w, tv.w, dot);
        }
        float s = fmaf(-2.f, dot, g_t2[n]);
        unsigned long long key =
            ((unsigned long long)enc_f32(s) << 32) | (unsigned)n;
        best = min(best, key);
    }
#pragma unroll
    for (int off = 16; off >= 1; off >>= 1)
        best = min(best, __shfl_xor_sync(0xffffffffu, best, off));
    if (lane == 0) g_best[q] = best;
}

// ---- MLP: 8 queries per CTA ----------------------------------------------
#define QB 8

__global__ void __launch_bounds__(256)
k_mlp(const float* __restrict__ train,
      const float* __restrict__ W1, const float* __restrict__ b1,
      const float* __restrict__ Wu, const float* __restrict__ bu,
      const float* __restrict__ Ws, const float* __restrict__ bs,
      float* __restrict__ out, int B) {
    __shared__ float x_s[QB][D];
    __shared__ float h_s[QB][H];
    const int qb  = blockIdx.x * QB;
    const int tid = threadIdx.x;

    if (tid < QB * (D / 4)) {
        int q  = tid >> 4;
        int c4 = tid & 15;
        unsigned ch = (unsigned)(g_best[qb + q] & 0xFFFFFFFFULL);
        ((float4*)&x_s[q][0])[c4] = __ldg(&((const float4*)train)[(size_t)ch * (D / 4) + c4]);
    }
    __syncthreads();

    {   // h = relu(x @ W1 + b1): thread owns columns tid, tid+256
        float a0[QB], a1[QB];
#pragma unroll
        for (int q = 0; q < QB; q++) { a0[q] = 0.f; a1[q] = 0.f; }
        const int c0 = tid, c1 = tid + 256;
#pragma unroll 4
        for (int d = 0; d < D; d++) {
            float w0 = __ldg(&W1[d * H + c0]);
            float w1 = __ldg(&W1[d * H + c1]);
#pragma unroll
            for (int q = 0; q < QB; q++) {
                float x = x_s[q][d];
                a0[q] = fmaf(x, w0, a0[q]);
                a1[q] = fmaf(x, w1, a1[q]);
            }
        }
        float bb0 = __ldg(&b1[c0]), bb1 = __ldg(&b1[c1]);
#pragma unroll
        for (int q = 0; q < QB; q++) {
            h_s[q][c0] = fmaxf(a0[q] + bb0, 0.f);
            h_s[q][c1] = fmaxf(a1[q] + bb1, 0.f);
        }
    }
    __syncthreads();

    {   // mu / logstd: (d, which, q-half of 4)
        const int d     = tid & 63;
        const int which = (tid >> 6) & 1;
        const int qh    = tid >> 7;           // 0/1
        const float* W  = which ? Ws : Wu;
        const float* bb = which ? bs : bu;
        float a[4] = {0.f, 0.f, 0.f, 0.f};
#pragma unroll 4
        for (int h = 0; h < H; h++) {
            float w = __ldg(&W[h * D + d]);
#pragma unroll
            for (int qq = 0; qq < 4; qq++)
                a[qq] = fmaf(h_s[qh * 4 + qq][h], w, a[qq]);
        }
        float bv = __ldg(&bb[d]);
#pragma unroll
        for (int qq = 0; qq < 4; qq++)
            out[(size_t)which * B * D + (size_t)(qb + qh * 4 + qq) * D + d] =
                a[qq] + bv;
    }
}

// ---- launch ---------------------------------------------------------------

extern "C" void kernel_launch(void* const* d_in, const int* in_sizes, int n_in,
                              void* d_out, int out_size) {
    const float* codes = (const float*)d_in[0];
    const float* train = (const float*)d_in[1];
    const float* W1    = (const float*)d_in[2];
    const float* b1    = (const float*)d_in[3];
    const float* Wu    = (const float*)d_in[4];
    const float* bu    = (const float*)d_in[5];
    const float* Ws    = (const float*)d_in[6];
    const float* bs    = (const float*)d_in[7];
    float* out = (float*)d_out;

    const int B = in_sizes[0] / D;   // 2048
    const int N = in_sizes[1] / D;   // 100000

    k_initcnt<<<(B + 255) / 256, 256>>>(B);
    k_t2<<<(NPAD + 255) / 256, 256>>>(train, N);

    const int tiles_total = (N + NT - 1) / NT;          // 782
    const int qtiles      = B / QT;                     // 16
    const int nsplits     = 9;                          // 144 CTAs
    const int tps         = (tiles_total + nsplits - 1) / nsplits;

    const size_t smem = (size_t)SMW * sizeof(uint32_t); // ~83.5 KB
    cudaFuncSetAttribute(k_score, cudaFuncAttributeMaxDynamicSharedMemorySize,
                         (int)smem);
    k_score<<<dim3(qtiles, nsplits), 256, smem>>>(codes, train, N,
                                                  tiles_total, tps);

    k_rescore<<<(B + 7) / 8, 256>>>(codes, train, B);
    k_mlp<<<B / QB, 256>>>(train, W1, b1, Wu, bu, Ws, bs, out, B);
}

// round 6
// speedup vs baseline: 1.8175x; 1.0515x over previous
#include <cuda_runtime.h>
#include <cstdint>

// ---------------------------------------------------------------------------
// PriorNetwork round 6: bf16 mma.sync.m16n8k16 approximate distances
// (conflict-free smem layout w/ parity XOR swizzle, CTA-shared running-min
// rescue, EPS=3.0 hard bound) + exact fp32 rescore + batched MLP.
// Legacy mma.sync only: harness targets plain sm_100 (no tcgen05).
// ---------------------------------------------------------------------------

#define D     64
#define H     512
#define QT    128      // queries per score CTA (M)
#define NT    128      // train rows per tile (N)
#define CAP   4096
#define EPS   3.0f
#define NPAD  100480
#define BQ    2048
#define QB    8

// smem word layout for k_score:
//   cmin : 128 words (per-query running min, enc'd)
//   t2b  : 2 * 128 floats
//   Bw   : 2 * 5120 words (128 n * 40-word stride; 32 k-pair words + 8 pad)
#define BSTRIDE 40
#define BWORDS  (NT * BSTRIDE)
#define SM_WORDS (128 + 256 + 2 * BWORDS)   // 10624 words = 42496 B

__device__ unsigned long long g_best[BQ];
__device__ float g_t2[NPAD];
__device__ int   g_ccnt[BQ];
__device__ int   g_cand[BQ * CAP];

// ---- helpers --------------------------------------------------------------

__device__ __forceinline__ unsigned enc_f32(float f) {
    unsigned u = __float_as_uint(f);
    return (u & 0x80000000u) ? ~u : (u | 0x80000000u);
}
__device__ __forceinline__ float dec_f32(unsigned e) {
    unsigned u = (e & 0x80000000u) ? (e ^ 0x80000000u) : ~e;
    return __uint_as_float(u);
}
__device__ __forceinline__ uint32_t bfp(float lo, float hi) {   // {lo,hi} bf16x2
    uint32_t r;
    asm("cvt.rn.satfinite.bf16x2.f32 %0, %1, %2;" : "=r"(r) : "f"(hi), "f"(lo));
    return r;
}
__device__ __forceinline__ void mma_bf16(float* c, const uint32_t* a,
                                         uint32_t b0, uint32_t b1) {
    asm("mma.sync.aligned.m16n8k16.row.col.f32.bf16.bf16.f32 "
        "{%0,%1,%2,%3}, {%4,%5,%6,%7}, {%8,%9}, {%0,%1,%2,%3};"
        : "+f"(c[0]), "+f"(c[1]), "+f"(c[2]), "+f"(c[3])
        : "r"(a[0]), "r"(a[1]), "r"(a[2]), "r"(a[3]), "r"(b0), "r"(b1));
}

// ---- small kernels --------------------------------------------------------

__global__ void k_initcnt(int B) {
    int i = blockIdx.x * blockDim.x + threadIdx.x;
    if (i < B) g_ccnt[i] = 0;
}

__global__ void k_t2(const float* __restrict__ train, int N) {
    int n = blockIdx.x * blockDim.x + threadIdx.x;
    if (n < NPAD) {
        if (n < N) {
            const float4* r = (const float4*)(train + (size_t)n * D);
            float s = 0.f;
#pragma unroll
            for (int k = 0; k < D / 4; k++) {
                float4 v = r[k];
                s += v.x * v.x + v.y * v.y + v.z * v.z + v.w * v.w;
            }
            g_t2[n] = s;
        } else {
            g_t2[n] = 3.0e38f;   // pads never win / never rescued
        }
    }
}

// ---- k_score --------------------------------------------------------------
// B smem word (before swizzle): Bw[n*40 + ks*8 + 2*r4 + h] = bf16x2 of
// train[n][k], k+1 with k = ks*16 + h*8 + 2*r4.  Parity XOR swizzle: word
// index ^= (n&1)<<1 on BOTH store and load -> STS and LDS fully conflict-free.

__device__ __forceinline__ void ldg_tile(float4 v[8], float4& t2r,
                                         const float* __restrict__ train,
                                         int n0, int N, int tid) {
#pragma unroll
    for (int k = 0; k < 8; k++) {
        int lin = tid + (k << 8);
        int n   = n0 + (lin >> 4);
        int c4  = lin & 15;
        v[k] = __ldg(&((const float4*)train)[(size_t)min(n, N - 1) * 16 + c4]);
    }
    if (tid < 32) t2r = *(const float4*)&g_t2[n0 + tid * 4];
}

__device__ __forceinline__ void sts_tile(uint32_t* __restrict__ Bw,
                                         float* __restrict__ t2buf,
                                         const float4 v[8], float4 t2r, int tid) {
#pragma unroll
    for (int k = 0; k < 8; k++) {
        int lin = tid + (k << 8);
        int n   = lin >> 4;
        int c4  = lin & 15;
        int k0  = c4 * 4;
        int ks  = k0 >> 4;
        int r   = k0 & 15;
        int h   = r >> 3;
        int r4a = (r & 7) >> 1;
        int w0  = ks * 8 + 2 * r4a + h;       // bit1 of w0 is always 0
        int px  = (n & 1) << 1;
        Bw[n * BSTRIDE + (w0 ^ px)]       = bfp(v[k].x, v[k].y);
        Bw[n * BSTRIDE + ((w0 + 2) ^ px)] = bfp(v[k].z, v[k].w);
    }
    if (tid < 32) *(float4*)&t2buf[tid * 4] = t2r;
}

__global__ void __launch_bounds__(256, 1)
k_score(const float* __restrict__ codes, const float* __restrict__ train,
        int N, int tiles_total, int tps) {
    extern __shared__ float smf[];
    unsigned* cmin = (unsigned*)smf;            // [128]
    float*    t2b  = smf + 128;                 // [2][128]
    uint32_t* Bw   = (uint32_t*)(smf + 384);    // [2][BWORDS]

    const int tid  = threadIdx.x;
    const int lane = tid & 31;
    const int wid  = tid >> 5;
    const int wm   = wid >> 1;                  // 0..3 : m32 strip
    const int wn   = wid & 1;                   // 0..1 : n64 strip
    const int g    = lane >> 2;                 // 0..7
    const int r4   = lane & 3;                  // 0..3
    const int px   = (g & 1) << 1;              // load-side parity swizzle
    const int qbase = blockIdx.x * QT;

    const int t0 = blockIdx.y * tps;
    const int t1 = min(t0 + tps, tiles_total);
    if (t0 >= t1) return;

    if (tid < QT) cmin[tid] = 0xFFFFFFFFu;

    // A fragments (bf16), hoisted once: afr[mi][ks][4]
    uint32_t afr[2][4][4];
#pragma unroll
    for (int mi = 0; mi < 2; mi++) {
        const int qr = qbase + wm * 32 + mi * 16 + g;
#pragma unroll
        for (int ks = 0; ks < 4; ks++) {
            const int k0 = ks * 16 + 2 * r4;
            float2 p0 = __ldg((const float2*)&codes[(size_t)qr * D + k0]);
            float2 p1 = __ldg((const float2*)&codes[(size_t)(qr + 8) * D + k0]);
            float2 p2 = __ldg((const float2*)&codes[(size_t)qr * D + k0 + 8]);
            float2 p3 = __ldg((const float2*)&codes[(size_t)(qr + 8) * D + k0 + 8]);
            afr[mi][ks][0] = bfp(p0.x, p0.y);
            afr[mi][ks][1] = bfp(p1.x, p1.y);
            afr[mi][ks][2] = bfp(p2.x, p2.y);
            afr[mi][ks][3] = bfp(p3.x, p3.y);
        }
    }

    // Local query row per slot (slot = mi*2 + rowhalf).
    int qloc[4];
#pragma unroll
    for (int s = 0; s < 4; s++)
        qloc[s] = wm * 32 + (s >> 1) * 16 + g + (s & 1) * 8;

    // Prologue: tile t0 into buffer 0.
    float4 v[8]; float4 t2r;
    ldg_tile(v, t2r, train, t0 * NT, N, tid);
    sts_tile(Bw, t2b, v, t2r, tid);
    __syncthreads();

    for (int t = t0; t < t1; t++) {
        const int p = (t - t0) & 1;
        const uint32_t* Bc  = Bw + p * BWORDS;
        const float*    t2c = t2b + p * 128;
        const int n0 = t * NT;

        if (t + 1 < t1) ldg_tile(v, t2r, train, (t + 1) * NT, N, tid);

        float acc[2][8][4];
#pragma unroll
        for (int mi = 0; mi < 2; mi++)
#pragma unroll
            for (int j = 0; j < 8; j++)
#pragma unroll
                for (int c = 0; c < 4; c++) acc[mi][j][c] = 0.f;

#pragma unroll
        for (int j = 0; j < 8; j++) {
            const int nrow = wn * 64 + j * 8 + g;
#pragma unroll
            for (int ks = 0; ks < 4; ks++) {
                uint2 b = *(const uint2*)&Bc[nrow * BSTRIDE +
                                             ((ks * 8 + 2 * r4) ^ px)];
                mma_bf16(acc[0][j], afr[0][ks], b.x, b.y);
                mma_bf16(acc[1][j], afr[1][ks], b.x, b.y);
            }
        }

        // Pass 1: per-slot tile minima -> shuffle across r4 -> shared cmin.
        float tm[4] = {3.4e38f, 3.4e38f, 3.4e38f, 3.4e38f};
#pragma unroll
        for (int j = 0; j < 8; j++) {
            float2 tv = *(const float2*)&t2c[wn * 64 + j * 8 + 2 * r4];
#pragma unroll
            for (int mi = 0; mi < 2; mi++)
#pragma unroll
                for (int c = 0; c < 4; c++) {
                    float s = fmaf(-2.f, acc[mi][j][c], (c & 1) ? tv.y : tv.x);
                    int slot = mi * 2 + (c >> 1);
                    tm[slot] = fminf(tm[slot], s);
                }
        }
#pragma unroll
        for (int s = 0; s < 4; s++) {
            tm[s] = fminf(tm[s], __shfl_xor_sync(0xffffffffu, tm[s], 1));
            tm[s] = fminf(tm[s], __shfl_xor_sync(0xffffffffu, tm[s], 2));
        }
        if (r4 == 0) {
#pragma unroll
            for (int s = 0; s < 4; s++)
                atomicMin(&cmin[qloc[s]], enc_f32(tm[s]));
        }
        __syncthreads();   // cmin includes this tile; mma reads of Bc done

        // Pass 2: rescue within EPS of the CTA-wide running min.
        float thr[4];
#pragma unroll
        for (int s = 0; s < 4; s++)
            thr[s] = dec_f32(cmin[qloc[s]]) + EPS;
#pragma unroll
        for (int j = 0; j < 8; j++) {
            float2 tv = *(const float2*)&t2c[wn * 64 + j * 8 + 2 * r4];
            const int nb = n0 + wn * 64 + j * 8 + 2 * r4;
#pragma unroll
            for (int mi = 0; mi < 2; mi++)
#pragma unroll
                for (int c = 0; c < 4; c++) {
                    float s = fmaf(-2.f, acc[mi][j][c], (c & 1) ? tv.y : tv.x);
                    int slot = mi * 2 + (c >> 1);
                    if (s <= thr[slot]) {
                        int q = qbase + qloc[slot];
                        int pos = atomicAdd(&g_ccnt[q], 1);
                        if (pos < CAP) g_cand[q * CAP + pos] = nb + (c & 1);
                    }
                }
        }

        if (t + 1 < t1) sts_tile(Bw + (p ^ 1) * BWORDS, t2b + (p ^ 1) * 128,
                                 v, t2r, tid);
        __syncthreads();   // next buffer published
    }
}

// ---- exact fp32 rescore (one warp per query) ------------------------------

__global__ void __launch_bounds__(256)
k_rescore(const float* __restrict__ codes, const float* __restrict__ train,
          int B) {
    const int lane = threadIdx.x & 31;
    const int q = blockIdx.x * 8 + (threadIdx.x >> 5);
    if (q >= B) return;

    float4 qv[16];
#pragma unroll
    for (int i = 0; i < 16; i++)
        qv[i] = __ldg(&((const float4*)codes)[(size_t)q * 16 + i]);

    unsigned long long best = 0xFFFFFFFFFFFFFFFFULL;
    int cnt = min(g_ccnt[q], CAP);
    for (int i = lane; i < cnt; i += 32) {
        int n = g_cand[q * CAP + i];
        const float4* tr = (const float4*)(train + (size_t)n * D);
        float dot = 0.f;
#pragma unroll
        for (int k = 0; k < 16; k++) {
            float4 tv = __ldg(&tr[k]);
            dot = fmaf(qv[k].x, tv.x, dot);
            dot = fmaf(qv[k].y, tv.y, dot);
            dot = fmaf(qv[k].z, tv.z, dot);
            dot = fmaf(qv[k].w, tv.w, dot);
        }
        float s = fmaf(-2.f, dot, g_t2[n]);
        unsigned long long key =
            ((unsigned long long)enc_f32(s) << 32) | (unsigned)n;
        best = min(best, key);
    }
#pragma unroll
    for (int off = 16; off >= 1; off >>= 1)
        best = min(best, __shfl_xor_sync(0xffffffffu, best, off));
    if (lane == 0) g_best[q] = best;
}

// ---- MLP: 8 queries per CTA ----------------------------------------------

__global__ void __launch_bounds__(256)
k_mlp(const float* __restrict__ train,
      const float* __restrict__ W1, const float* __restrict__ b1,
      const float* __restrict__ Wu, const float* __restrict__ bu,
      const float* __restrict__ Ws, const float* __restrict__ bs,
      float* __restrict__ out, int B) {
    __shared__ float x_s[QB][D];
    __shared__ float h_s[QB][H];
    const int qb  = blockIdx.x * QB;
    const int tid = threadIdx.x;

    if (tid < QB * (D / 4)) {
        int q  = tid >> 4;
        int c4 = tid & 15;
        unsigned ch = (unsigned)(g_best[qb + q] & 0xFFFFFFFFULL);
        ((float4*)&x_s[q][0])[c4] =
            __ldg(&((const float4*)train)[(size_t)ch * (D / 4) + c4]);
    }
    __syncthreads();

    {   // h = relu(x @ W1 + b1): thread owns columns tid, tid+256
        float a0[QB], a1[QB];
#pragma unroll
        for (int q = 0; q < QB; q++) { a0[q] = 0.f; a1[q] = 0.f; }
        const int c0 = tid, c1 = tid + 256;
#pragma unroll 4
        for (int d = 0; d < D; d++) {
            float w0 = __ldg(&W1[d * H + c0]);
            float w1 = __ldg(&W1[d * H + c1]);
#pragma unroll
            for (int q = 0; q < QB; q++) {
                float x = x_s[q][d];
                a0[q] = fmaf(x, w0, a0[q]);
                a1[q] = fmaf(x, w1, a1[q]);
            }
        }
        float bb0 = __ldg(&b1[c0]), bb1 = __ldg(&b1[c1]);
#pragma unroll
        for (int q = 0; q < QB; q++) {
            h_s[q][c0] = fmaxf(a0[q] + bb0, 0.f);
            h_s[q][c1] = fmaxf(a1[q] + bb1, 0.f);
        }
    }
    __syncthreads();

    {   // mu / logstd
        const int d     = tid & 63;
        const int which = (tid >> 6) & 1;
        const int qh    = tid >> 7;
        const float* W  = which ? Ws : Wu;
        const float* bb = which ? bs : bu;
        float a[4] = {0.f, 0.f, 0.f, 0.f};
#pragma unroll 4
        for (int h = 0; h < H; h++) {
            float w = __ldg(&W[h * D + d]);
#pragma unroll
            for (int qq = 0; qq < 4; qq++)
                a[qq] = fmaf(h_s[qh * 4 + qq][h], w, a[qq]);
        }
        float bvv = __ldg(&bb[d]);
#pragma unroll
        for (int qq = 0; qq < 4; qq++)
            out[(size_t)which * B * D + (size_t)(qb + qh * 4 + qq) * D + d] =
                a[qq] + bvv;
    }
}

// ---- launch ---------------------------------------------------------------

extern "C" void kernel_launch(void* const* d_in, const int* in_sizes, int n_in,
                              void* d_out, int out_size) {
    const float* codes = (const float*)d_in[0];
    const float* train = (const float*)d_in[1];
    const float* W1    = (const float*)d_in[2];
    const float* b1    = (const float*)d_in[3];
    const float* Wu    = (const float*)d_in[4];
    const float* bu    = (const float*)d_in[5];
    const float* Ws    = (const float*)d_in[6];
    const float* bs    = (const float*)d_in[7];
    float* out = (float*)d_out;

    const int B = in_sizes[0] / D;   // 2048
    const int N = in_sizes[1] / D;   // 100000

    k_initcnt<<<(B + 255) / 256, 256>>>(B);
    k_t2<<<(NPAD + 255) / 256, 256>>>(train, N);

    const int tiles_total = (N + NT - 1) / NT;          // 782
    const int qtiles      = B / QT;                     // 16
    const int nsplits     = 9;                          // 144 CTAs, 1 wave
    const int tps         = (tiles_total + nsplits - 1) / nsplits;

    const size_t smem = (size_t)SM_WORDS * sizeof(float);   // 42496 B
    cudaFuncSetAttribute(k_score, cudaFuncAttributeMaxDynamicSharedMemorySize,
                         (int)smem);
    k_score<<<dim3(qtiles, nsplits), 256, smem>>>(codes, train, N,
                                                  tiles_total, tps);

    k_rescore<<<(B + 7) / 8, 256>>>(codes, train, B);
    k_mlp<<<B / QB, 256>>>(train, W1, b1, Wu, bu, Ws, bs, out, B);
}